// round 4
// baseline (speedup 1.0000x reference)
#include <cuda_runtime.h>
#include <math.h>
#include <stdint.h>

#define BATCH   64
#define NPRI    8732
#define NCLS    81
#define NPRIORS (BATCH * NPRI)
#define SIGNBIT 0x80000000u

// Scratch (__device__ globals: allocation-free rule)
__device__ unsigned g_conf[NPRIORS];   // conf_loss bits; sign bit = positive prior
__device__ unsigned g_locv[NPRIORS];   // loc smooth-L1 row sum bits; sign bit = counted row
__device__ float    g_batch[BATCH];
__device__ int      g_done = 0;

// ---------------------------------------------------------------------------
// Kernel 1: streaming pass. Warp-autonomous: each warp owns 4 rows.
// Fused pred_conf/gt_conf load loop: the lane that sees the one-hot 1.0 also
// holds the target logit (same float4 index) -> record tl directly.
// ---------------------------------------------------------------------------
__global__ void __launch_bounds__(256)
k_main(const float* __restrict__ pred_conf,
       const float* __restrict__ pred_loc,
       const float* __restrict__ gt_conf,
       const float* __restrict__ gt_loc) {
    __shared__ float s_conf[8][4 * NCLS];   // 324 floats per warp slice
    __shared__ float s_tl[8][4];
    __shared__ int   s_pos[8][4];

    int w    = threadIdx.x >> 5;
    int lane = threadIdx.x & 31;
    size_t row0 = ((size_t)blockIdx.x * 8 + w) * 4;   // first of this warp's 4 rows

    const float4* cp = (const float4*)(pred_conf + row0 * NCLS);
    const float4* gp = (const float4*)(gt_conf  + row0 * NCLS);
    float* sc = s_conf[w];

    // Fused staging + one-hot scan: 81 float4 per stream, 3 iterations.
    #pragma unroll
    for (int ii = 0; ii < 3; ii++) {
        int i = lane + 32 * ii;
        if (i < 81) {
            float4 p = __ldcs(cp + i);
            float4 g = __ldcs(gp + i);
            ((float4*)sc)[i] = p;
            int flat = i * 4;
            if (g.x != 0.0f) { int r = flat / NCLS;       int c = flat     - r * NCLS; s_tl[w][r] = p.x; s_pos[w][r] = (c != 0); }
            if (g.y != 0.0f) { int r = (flat + 1) / NCLS; int c = flat + 1 - r * NCLS; s_tl[w][r] = p.y; s_pos[w][r] = (c != 0); }
            if (g.z != 0.0f) { int r = (flat + 2) / NCLS; int c = flat + 2 - r * NCLS; s_tl[w][r] = p.z; s_pos[w][r] = (c != 0); }
            if (g.w != 0.0f) { int r = (flat + 3) / NCLS; int c = flat + 3 - r * NCLS; s_tl[w][r] = p.w; s_pos[w][r] = (c != 0); }
        }
    }

    // Localization: lanes 0..3, one row each (float4 per row, 16B-aligned).
    if (lane < 4) {
        size_t row = row0 + lane;
        float4 pl = __ldcs((const float4*)pred_loc + row);
        float4 gl = __ldcs((const float4*)gt_loc  + row);
        float s = 0.0f;
        bool any = false;
        if (gl.x != 0.0f) { any = true; float d = fabsf(pl.x - gl.x); s += (d < 1.0f) ? 0.5f*d*d : d - 0.5f; }
        if (gl.y != 0.0f) { any = true; float d = fabsf(pl.y - gl.y); s += (d < 1.0f) ? 0.5f*d*d : d - 0.5f; }
        if (gl.z != 0.0f) { any = true; float d = fabsf(pl.z - gl.z); s += (d < 1.0f) ? 0.5f*d*d : d - 0.5f; }
        if (gl.w != 0.0f) { any = true; float d = fabsf(pl.w - gl.w); s += (d < 1.0f) ? 0.5f*d*d : d - 0.5f; }
        unsigned u = __float_as_uint(s);
        if (any) u |= SIGNBIT;
        g_locv[row] = u;
    }
    __syncwarp();

    // Compute: 8 threads per row (4 rows per warp); shfl offsets 4,2,1 stay
    // inside each 8-lane group.
    int sub = lane & 7;
    int r   = lane >> 3;
    const float* rowp = sc + r * NCLS;

    float v[10];
    #pragma unroll
    for (int k = 0; k < 10; k++) v[k] = rowp[sub + 8 * k];

    float m = v[0];
    #pragma unroll
    for (int k = 1; k < 10; k++) m = fmaxf(m, v[k]);
    float vlast = 0.0f;
    if (sub == 0) { vlast = rowp[80]; m = fmaxf(m, vlast); }
    #pragma unroll
    for (int o = 4; o; o >>= 1) m = fmaxf(m, __shfl_xor_sync(0xFFFFFFFFu, m, o));

    float s = 0.0f;
    #pragma unroll
    for (int k = 0; k < 10; k++) s += __expf(v[k] - m);
    if (sub == 0) s += __expf(vlast - m);
    #pragma unroll
    for (int o = 4; o; o >>= 1) s += __shfl_xor_sync(0xFFFFFFFFu, s, o);

    if (sub == 0) {
        float closs = fmaxf(m + __logf(s) - s_tl[w][r], 0.0f);  // CE >= 0
        unsigned u = __float_as_uint(closs);
        if (s_pos[w][r]) u |= SIGNBIT;                          // positive-prior flag
        g_conf[row0 + r] = u;
    }
}

// ---------------------------------------------------------------------------
// Warp-parallel bin select for an MSD radix pass (call with tid<32).
// ---------------------------------------------------------------------------
__device__ __forceinline__ void select_bin(const int* hist, int sh,
                                           unsigned* s_prefix, int* s_kk,
                                           int lane) {
    int kk = *s_kk;
    unsigned pref = *s_prefix;
    int base = lane * 8;
    int h[8];
    int T = 0;
    #pragma unroll
    for (int j = 0; j < 8; j++) { h[j] = hist[base + j]; T += h[j]; }
    int ssum = T;   // inclusive suffix-sum across lanes
    #pragma unroll
    for (int o = 1; o < 32; o <<= 1) {
        int vv = __shfl_down_sync(0xFFFFFFFFu, ssum, o);
        if (lane + o < 32) ssum += vv;
    }
    int excl = ssum - T;
    if (excl <= kk && kk < ssum) {
        int c = excl;
        #pragma unroll
        for (int j = 7; j >= 0; j--) {
            if (c + h[j] > kk) {
                *s_prefix = pref | ((unsigned)(base + j) << sh);
                *s_kk = kk - c;
                break;
            }
            c += h[j];
        }
    }
}

// ---------------------------------------------------------------------------
// Kernel 2: per-batch hard-negative mining + combine. One CTA per batch row.
// 2 full sweeps + candidate-compacted radix (bins above the pass-1 bin are
// unconditionally above-threshold; only the pass-1 bin needs refinement).
// ---------------------------------------------------------------------------
__global__ void __launch_bounds__(1024)
k_finish(float* __restrict__ out) {
    __shared__ unsigned sbits[NPRI];     // 34928 B
    __shared__ unsigned cand[NPRI];      // pass-1-bin candidates
    __shared__ int   hist[256];
    __shared__ float sredf[64];
    __shared__ int   sredi[64];
    __shared__ int   s_kk, s_cnt;
    __shared__ unsigned s_prefix;
    __shared__ int   s_np, s_loccnt;
    __shared__ float s_possum, s_locsum, s_above;
    __shared__ int   s_islast;

    int b   = blockIdx.x;
    int tid = threadIdx.x;
    int w = tid >> 5, lane = tid & 31;

    if (tid < 256) hist[tid] = 0;
    if (tid == 0) { s_cnt = 0; s_above = 0.0f; }
    __syncthreads();

    // Sweep 1: vector load + classify + top-byte histogram.
    const uint4* gc = (const uint4*)(g_conf + (size_t)b * NPRI);
    const uint4* gl = (const uint4*)(g_locv + (size_t)b * NPRI);
    float pos_sum = 0.0f, loc_sum = 0.0f;
    int   pos_cnt = 0,    loc_cnt = 0;
    for (int i = tid; i < NPRI / 4; i += 1024) {
        uint4 u = gc[i];
        #pragma unroll
        for (int j = 0; j < 4; j++) {
            unsigned* uc = &((unsigned*)&u)[j];
            if (*uc & SIGNBIT) {
                pos_cnt++; pos_sum += __uint_as_float(*uc & ~SIGNBIT);
                *uc = 0u;
            }
            atomicAdd(&hist[*uc >> 24], 1);
        }
        ((uint4*)sbits)[i] = u;
        uint4 v = gl[i];
        #pragma unroll
        for (int j = 0; j < 4; j++) {
            unsigned ul = ((unsigned*)&v)[j];
            if (ul & SIGNBIT) { loc_cnt++; loc_sum += __uint_as_float(ul & ~SIGNBIT); }
        }
    }
    #pragma unroll
    for (int o = 16; o; o >>= 1) {
        pos_cnt += __shfl_xor_sync(0xFFFFFFFFu, pos_cnt, o);
        loc_cnt += __shfl_xor_sync(0xFFFFFFFFu, loc_cnt, o);
        pos_sum += __shfl_xor_sync(0xFFFFFFFFu, pos_sum, o);
        loc_sum += __shfl_xor_sync(0xFFFFFFFFu, loc_sum, o);
    }
    if (lane == 0) {
        sredi[w] = pos_cnt; sredi[32 + w] = loc_cnt;
        sredf[w] = pos_sum; sredf[32 + w] = loc_sum;
    }
    __syncthreads();
    if (tid < 32) {
        int   pc = sredi[tid], lc = sredi[32 + tid];
        float ps = sredf[tid]; float ls = sredf[32 + tid];
        #pragma unroll
        for (int o = 16; o; o >>= 1) {
            pc += __shfl_xor_sync(0xFFFFFFFFu, pc, o);
            lc += __shfl_xor_sync(0xFFFFFFFFu, lc, o);
            ps += __shfl_xor_sync(0xFFFFFFFFu, ps, o);
            ls += __shfl_xor_sync(0xFFFFFFFFu, ls, o);
        }
        if (tid == 0) {
            s_np = pc; s_loccnt = lc; s_possum = ps; s_locsum = ls;
            int kk = (int)((float)pc * 3.0f);
            if (kk > NPRI - 1) kk = NPRI - 1;
            if (kk < 0) kk = 0;
            s_kk = kk;
            s_prefix = 0u;
        }
    }
    __syncthreads();

    // Pass-1 select (histogram built during sweep 1); s_kk becomes in-bin rank.
    if (tid < 32) select_bin(hist, 24, &s_prefix, &s_kk, lane);
    __syncthreads();

    unsigned bin1 = s_prefix >> 24;

    // Sweep 2: compact pass-1-bin candidates; sum bins above (all > thresh).
    float above = 0.0f;
    for (int i = tid; i < NPRI / 4; i += 1024) {
        uint4 u = ((const uint4*)sbits)[i];
        #pragma unroll
        for (int j = 0; j < 4; j++) {
            unsigned uc = ((unsigned*)&u)[j];
            unsigned tb = uc >> 24;
            if (tb > bin1) above += __uint_as_float(uc);
            else if (tb == bin1) cand[atomicAdd(&s_cnt, 1)] = uc;
        }
    }
    #pragma unroll
    for (int o = 16; o; o >>= 1) above += __shfl_xor_sync(0xFFFFFFFFu, above, o);
    if (lane == 0) sredf[w] = above;
    __syncthreads();
    if (tid < 32) {
        float vv = sredf[tid];
        #pragma unroll
        for (int o = 16; o; o >>= 1) vv += __shfl_xor_sync(0xFFFFFFFFu, vv, o);
        if (tid == 0) s_above = vv;
    }
    __syncthreads();

    int cnt = s_cnt;

    // Radix passes 2..4 over candidates only.
    #pragma unroll
    for (int sh = 16; sh >= 0; sh -= 8) {
        if (tid < 256) hist[tid] = 0;
        __syncthreads();
        unsigned himask = 0xFFFFFFFFu << (sh + 8);
        unsigned pref   = s_prefix;
        for (int i = tid; i < cnt; i += 1024) {
            unsigned u = cand[i];
            if ((u & himask) == pref)
                atomicAdd(&hist[(u >> sh) & 0xFFu], 1);
        }
        __syncthreads();
        if (tid < 32) select_bin(hist, sh, &s_prefix, &s_kk, lane);
        __syncthreads();
    }

    float thresh = __uint_as_float(s_prefix);   // exact value at rank k

    // In-bin candidates strictly above threshold.
    float local = 0.0f;
    for (int i = tid; i < cnt; i += 1024) {
        float f = __uint_as_float(cand[i]);
        if (f > thresh) local += f;
    }
    #pragma unroll
    for (int o = 16; o; o >>= 1) local += __shfl_xor_sync(0xFFFFFFFFu, local, o);
    if (lane == 0) sredf[w] = local;
    __syncthreads();
    if (tid < 32) {
        float vv = sredf[tid];
        #pragma unroll
        for (int o = 16; o; o >>= 1) vv += __shfl_xor_sync(0xFFFFFFFFu, vv, o);
        if (tid == 0) {
            float neg = vv + s_above;
            float fnp = (float)s_np;
            float conf_total = s_possum / fnp + neg / (fnp * 3.0f);
            float loc_total  = s_locsum / (float)s_loccnt;
            g_batch[b] = conf_total + loc_total;
            __threadfence();
            int done = atomicAdd(&g_done, 1);
            s_islast = (done == BATCH - 1);
        }
    }
    __syncthreads();
    if (s_islast && tid < 32) {
        float t = g_batch[tid] + g_batch[tid + 32];
        #pragma unroll
        for (int o = 16; o; o >>= 1) t += __shfl_xor_sync(0xFFFFFFFFu, t, o);
        if (tid == 0) {
            out[0] = t * (1.0f / (float)BATCH);
            g_done = 0;                          // reset for next graph replay
        }
    }
}

// ---------------------------------------------------------------------------
extern "C" void kernel_launch(void* const* d_in, const int* in_sizes, int n_in,
                              void* d_out, int out_size) {
    const float* pred_conf = (const float*)d_in[0];
    const float* pred_loc  = (const float*)d_in[1];
    const float* gt_conf   = (const float*)d_in[2];
    const float* gt_loc    = (const float*)d_in[3];
    float* out = (float*)d_out;

    k_main<<<NPRIORS / 32, 256>>>(pred_conf, pred_loc, gt_conf, gt_loc);
    k_finish<<<BATCH, 1024>>>(out);
}

// round 5
// speedup vs baseline: 1.1046x; 1.1046x over previous
#include <cuda_runtime.h>
#include <math.h>
#include <stdint.h>

#define BATCH   64
#define NPRI    8732
#define NCLS    81
#define NPRIORS (BATCH * NPRI)
#define NCHUNKS (NPRIORS / 4)        // 139712 chunks of 4 rows
#define KM_CTAS 592                  // 148 SMs x 4 CTAs: single wave
#define KM_WPC  8
#define KM_STRIDE (KM_CTAS * KM_WPC) // 4736 warps
#define SIGNBIT 0x80000000u

// Scratch (__device__ globals: allocation-free rule)
__device__ unsigned g_conf[NPRIORS];   // conf_loss bits; sign bit = positive prior
__device__ unsigned g_locv[NPRIORS];   // loc smooth-L1 row sum bits; sign bit = counted row
__device__ float    g_batch[BATCH];
__device__ int      g_done = 0;

// ---------------------------------------------------------------------------
__device__ __forceinline__ void scan4(float4 g, float4 p, int flat,
                                      float* tl, int* pos) {
    if (g.x != 0.0f) { int r = flat / NCLS;       int c = flat     - r * NCLS; tl[r] = p.x; pos[r] = (c != 0); }
    if (g.y != 0.0f) { int r = (flat + 1) / NCLS; int c = flat + 1 - r * NCLS; tl[r] = p.y; pos[r] = (c != 0); }
    if (g.z != 0.0f) { int r = (flat + 2) / NCLS; int c = flat + 2 - r * NCLS; tl[r] = p.z; pos[r] = (c != 0); }
    if (g.w != 0.0f) { int r = (flat + 3) / NCLS; int c = flat + 3 - r * NCLS; tl[r] = p.w; pos[r] = (c != 0); }
}

__device__ __forceinline__ void write_loc(float4 pl, float4 gl, size_t row) {
    float s = 0.0f; bool any = false;
    if (gl.x != 0.0f) { any = true; float d = fabsf(pl.x - gl.x); s += (d < 1.0f) ? 0.5f*d*d : d - 0.5f; }
    if (gl.y != 0.0f) { any = true; float d = fabsf(pl.y - gl.y); s += (d < 1.0f) ? 0.5f*d*d : d - 0.5f; }
    if (gl.z != 0.0f) { any = true; float d = fabsf(pl.z - gl.z); s += (d < 1.0f) ? 0.5f*d*d : d - 0.5f; }
    if (gl.w != 0.0f) { any = true; float d = fabsf(pl.w - gl.w); s += (d < 1.0f) ? 0.5f*d*d : d - 0.5f; }
    unsigned u = __float_as_uint(s);
    if (any) u |= SIGNBIT;
    g_locv[row] = u;
}

// ---------------------------------------------------------------------------
// Kernel 1: persistent streaming pass, double-buffered per-warp pipeline.
// Each warp owns a chunk of 4 rows per iteration; loads for chunk i+1 are in
// flight while chunk i is computed from smem.
// ---------------------------------------------------------------------------
__global__ void __launch_bounds__(256, 4)
k_main(const float* __restrict__ pred_conf,
       const float* __restrict__ pred_loc,
       const float* __restrict__ gt_conf,
       const float* __restrict__ gt_loc) {
    __shared__ float s_conf[KM_WPC][2][4 * NCLS];   // 324 floats per buffer
    __shared__ float s_tl [KM_WPC][2][4];
    __shared__ int   s_pos[KM_WPC][2][4];

    const int w    = threadIdx.x >> 5;
    const int lane = threadIdx.x & 31;
    const int sub  = lane & 7;
    const int r    = lane >> 3;
    const float4* cp4 = (const float4*)pred_conf;
    const float4* gp4 = (const float4*)gt_conf;
    const float4* pl4 = (const float4*)pred_loc;
    const float4* gl4 = (const float4*)gt_loc;

    int cur = blockIdx.x * KM_WPC + w;     // first chunk (always < NCHUNKS)

    float4 p0, p1, p2, plq, glq;
    p2 = make_float4(0,0,0,0); plq = p2; glq = p2;

    // ---- prologue: load + scan + stage chunk `cur` into buffer 0
    {
        size_t fb = (size_t)cur * 81;
        p0 = __ldcs(cp4 + fb + lane);
        p1 = __ldcs(cp4 + fb + lane + 32);
        float4 g0 = __ldcs(gp4 + fb + lane);
        float4 g1 = __ldcs(gp4 + fb + lane + 32);
        float4 g2 = make_float4(0,0,0,0);
        if (lane < 17) { p2 = __ldcs(cp4 + fb + lane + 64); g2 = __ldcs(gp4 + fb + lane + 64); }
        if (lane < 4)  { plq = __ldcs(pl4 + (size_t)cur * 4 + lane); glq = __ldcs(gl4 + (size_t)cur * 4 + lane); }
        scan4(g0, p0, lane * 4,        s_tl[w][0], s_pos[w][0]);
        scan4(g1, p1, (lane + 32) * 4, s_tl[w][0], s_pos[w][0]);
        if (lane < 17) scan4(g2, p2, (lane + 64) * 4, s_tl[w][0], s_pos[w][0]);
        float4* sc = (float4*)s_conf[w][0];
        sc[lane] = p0; sc[lane + 32] = p1;
        if (lane < 17) sc[lane + 64] = p2;
        if (lane < 4) write_loc(plq, glq, (size_t)cur * 4 + lane);
    }
    __syncwarp();

    int buf = 0;
    int cn  = cur + KM_STRIDE;
    while (cur < NCHUNKS) {
        bool hn = (cn < NCHUNKS);
        if (hn) {   // issue loads for next chunk; scan one-hot immediately
            size_t fb = (size_t)cn * 81;
            p0 = __ldcs(cp4 + fb + lane);
            p1 = __ldcs(cp4 + fb + lane + 32);
            float4 g0 = __ldcs(gp4 + fb + lane);
            float4 g1 = __ldcs(gp4 + fb + lane + 32);
            float4 g2 = make_float4(0,0,0,0);
            if (lane < 17) { p2 = __ldcs(cp4 + fb + lane + 64); g2 = __ldcs(gp4 + fb + lane + 64); }
            if (lane < 4)  { plq = __ldcs(pl4 + (size_t)cn * 4 + lane); glq = __ldcs(gl4 + (size_t)cn * 4 + lane); }
            scan4(g0, p0, lane * 4,        s_tl[w][buf ^ 1], s_pos[w][buf ^ 1]);
            scan4(g1, p1, (lane + 32) * 4, s_tl[w][buf ^ 1], s_pos[w][buf ^ 1]);
            if (lane < 17) scan4(g2, p2, (lane + 64) * 4, s_tl[w][buf ^ 1], s_pos[w][buf ^ 1]);
        }

        // ---- compute current chunk from smem (8 threads per row)
        {
            const float* rowp = s_conf[w][buf] + r * NCLS;
            float v[10];
            #pragma unroll
            for (int k = 0; k < 10; k++) v[k] = rowp[sub + 8 * k];
            float m = v[0];
            #pragma unroll
            for (int k = 1; k < 10; k++) m = fmaxf(m, v[k]);
            float vlast = 0.0f;
            if (sub == 0) { vlast = rowp[80]; m = fmaxf(m, vlast); }
            #pragma unroll
            for (int o = 4; o; o >>= 1) m = fmaxf(m, __shfl_xor_sync(0xFFFFFFFFu, m, o));
            float s = 0.0f;
            #pragma unroll
            for (int k = 0; k < 10; k++) s += __expf(v[k] - m);
            if (sub == 0) s += __expf(vlast - m);
            #pragma unroll
            for (int o = 4; o; o >>= 1) s += __shfl_xor_sync(0xFFFFFFFFu, s, o);
            if (sub == 0) {
                float closs = fmaxf(m + __logf(s) - s_tl[w][buf][r], 0.0f);
                unsigned u = __float_as_uint(closs);
                if (s_pos[w][buf][r]) u |= SIGNBIT;
                g_conf[(size_t)cur * 4 + r] = u;
            }
        }
        __syncwarp();

        if (hn) {   // stage next chunk into the other buffer
            float4* sc = (float4*)s_conf[w][buf ^ 1];
            sc[lane] = p0; sc[lane + 32] = p1;
            if (lane < 17) sc[lane + 64] = p2;
            if (lane < 4) write_loc(plq, glq, (size_t)cn * 4 + lane);
        }
        __syncwarp();
        cur = cn; cn += KM_STRIDE; buf ^= 1;
    }
}

// ---------------------------------------------------------------------------
// Warp-parallel bin select for an MSD radix pass (call with tid<32).
// ---------------------------------------------------------------------------
__device__ __forceinline__ void select_bin(const int* hist, int sh,
                                           unsigned* s_prefix, int* s_kk,
                                           int lane) {
    int kk = *s_kk;
    unsigned pref = *s_prefix;
    int base = lane * 8;
    int h[8];
    int T = 0;
    #pragma unroll
    for (int j = 0; j < 8; j++) { h[j] = hist[base + j]; T += h[j]; }
    int ssum = T;   // inclusive suffix-sum across lanes
    #pragma unroll
    for (int o = 1; o < 32; o <<= 1) {
        int vv = __shfl_down_sync(0xFFFFFFFFu, ssum, o);
        if (lane + o < 32) ssum += vv;
    }
    int excl = ssum - T;
    if (excl <= kk && kk < ssum) {
        int c = excl;
        #pragma unroll
        for (int j = 7; j >= 0; j--) {
            if (c + h[j] > kk) {
                *s_prefix = pref | ((unsigned)(base + j) << sh);
                *s_kk = kk - c;
                break;
            }
            c += h[j];
        }
    }
}

// ---------------------------------------------------------------------------
// Kernel 2: per-batch hard-negative mining + combine. One CTA per batch row.
// Histogram & compaction use warp-aggregated atomics (hot-bin fix).
// ---------------------------------------------------------------------------
__global__ void __launch_bounds__(1024)
k_finish(float* __restrict__ out) {
    __shared__ unsigned sbits[NPRI];     // 34928 B
    __shared__ unsigned cand[NPRI];      // pass-1-bin candidates
    __shared__ int   hist[256];
    __shared__ float sredf[64];
    __shared__ int   sredi[64];
    __shared__ int   s_kk, s_cnt;
    __shared__ unsigned s_prefix;
    __shared__ int   s_np, s_loccnt;
    __shared__ float s_possum, s_locsum, s_above;
    __shared__ int   s_islast;

    int b   = blockIdx.x;
    int tid = threadIdx.x;
    int w = tid >> 5, lane = tid & 31;

    if (tid < 256) hist[tid] = 0;
    if (tid == 0) { s_cnt = 0; s_above = 0.0f; }
    __syncthreads();

    const uint4* gc = (const uint4*)(g_conf + (size_t)b * NPRI);
    const uint4* gl = (const uint4*)(g_locv + (size_t)b * NPRI);
    const int N4 = NPRI / 4;                 // 2183
    const int NIT = (N4 + 1023) / 1024;      // 3

    // Sweep 1: load + classify + warp-aggregated top-byte histogram.
    float pos_sum = 0.0f, loc_sum = 0.0f;
    int   pos_cnt = 0,    loc_cnt = 0;
    for (int it = 0; it < NIT; it++) {
        int i = it * 1024 + tid;
        bool valid = (i < N4);
        unsigned act = __ballot_sync(0xFFFFFFFFu, valid);
        if (valid) {
            uint4 u = gc[i];
            #pragma unroll
            for (int j = 0; j < 4; j++) {
                unsigned* uc = &((unsigned*)&u)[j];
                if (*uc & SIGNBIT) {
                    pos_cnt++; pos_sum += __uint_as_float(*uc & ~SIGNBIT);
                    *uc = 0u;
                }
                unsigned bin = *uc >> 24;
                unsigned mset = __match_any_sync(act, bin);
                if ((unsigned)(__ffs(mset) - 1) == (unsigned)lane)
                    atomicAdd(&hist[bin], __popc(mset));
            }
            ((uint4*)sbits)[i] = u;
            uint4 v = gl[i];
            #pragma unroll
            for (int j = 0; j < 4; j++) {
                unsigned ul = ((unsigned*)&v)[j];
                if (ul & SIGNBIT) { loc_cnt++; loc_sum += __uint_as_float(ul & ~SIGNBIT); }
            }
        }
    }
    #pragma unroll
    for (int o = 16; o; o >>= 1) {
        pos_cnt += __shfl_xor_sync(0xFFFFFFFFu, pos_cnt, o);
        loc_cnt += __shfl_xor_sync(0xFFFFFFFFu, loc_cnt, o);
        pos_sum += __shfl_xor_sync(0xFFFFFFFFu, pos_sum, o);
        loc_sum += __shfl_xor_sync(0xFFFFFFFFu, loc_sum, o);
    }
    if (lane == 0) {
        sredi[w] = pos_cnt; sredi[32 + w] = loc_cnt;
        sredf[w] = pos_sum; sredf[32 + w] = loc_sum;
    }
    __syncthreads();
    if (tid < 32) {
        int   pc = sredi[tid], lc = sredi[32 + tid];
        float ps = sredf[tid]; float ls = sredf[32 + tid];
        #pragma unroll
        for (int o = 16; o; o >>= 1) {
            pc += __shfl_xor_sync(0xFFFFFFFFu, pc, o);
            lc += __shfl_xor_sync(0xFFFFFFFFu, lc, o);
            ps += __shfl_xor_sync(0xFFFFFFFFu, ps, o);
            ls += __shfl_xor_sync(0xFFFFFFFFu, ls, o);
        }
        if (tid == 0) {
            s_np = pc; s_loccnt = lc; s_possum = ps; s_locsum = ls;
            int kk = (int)((float)pc * 3.0f);
            if (kk > NPRI - 1) kk = NPRI - 1;
            if (kk < 0) kk = 0;
            s_kk = kk;
            s_prefix = 0u;
        }
    }
    __syncthreads();

    // Pass-1 select; s_kk becomes the in-bin rank.
    if (tid < 32) select_bin(hist, 24, &s_prefix, &s_kk, lane);
    __syncthreads();

    unsigned bin1 = s_prefix >> 24;

    // Sweep 2: warp-aggregated compaction of pass-1-bin candidates;
    // bins above bin1 are unconditionally above-threshold -> sum directly.
    float above = 0.0f;
    for (int it = 0; it < NIT; it++) {
        int i = it * 1024 + tid;
        bool valid = (i < N4);
        unsigned act = __ballot_sync(0xFFFFFFFFu, valid);
        if (valid) {
            uint4 u = ((const uint4*)sbits)[i];
            #pragma unroll
            for (int j = 0; j < 4; j++) {
                unsigned uc = ((unsigned*)&u)[j];
                unsigned tb = uc >> 24;
                if (tb > bin1) above += __uint_as_float(uc);
                bool isc = (tb == bin1);
                unsigned cm = __ballot_sync(act, isc);
                if (isc) {
                    int leader = __ffs(cm) - 1;
                    int mypos = __popc(cm & ((1u << lane) - 1u));
                    int base = 0;
                    if (lane == leader) base = atomicAdd(&s_cnt, __popc(cm));
                    base = __shfl_sync(cm, base, leader);
                    cand[base + mypos] = uc;
                }
            }
        }
    }
    #pragma unroll
    for (int o = 16; o; o >>= 1) above += __shfl_xor_sync(0xFFFFFFFFu, above, o);
    if (lane == 0) sredf[w] = above;
    __syncthreads();
    if (tid < 32) {
        float vv = sredf[tid];
        #pragma unroll
        for (int o = 16; o; o >>= 1) vv += __shfl_xor_sync(0xFFFFFFFFu, vv, o);
        if (tid == 0) s_above = vv;
    }
    __syncthreads();

    int cnt = s_cnt;

    // Radix passes 2..4 over candidates only (mantissa bytes: spread bins).
    #pragma unroll
    for (int sh = 16; sh >= 0; sh -= 8) {
        if (tid < 256) hist[tid] = 0;
        __syncthreads();
        unsigned himask = 0xFFFFFFFFu << (sh + 8);
        unsigned pref   = s_prefix;
        for (int i = tid; i < cnt; i += 1024) {
            unsigned u = cand[i];
            if ((u & himask) == pref)
                atomicAdd(&hist[(u >> sh) & 0xFFu], 1);
        }
        __syncthreads();
        if (tid < 32) select_bin(hist, sh, &s_prefix, &s_kk, lane);
        __syncthreads();
    }

    float thresh = __uint_as_float(s_prefix);   // exact value at rank k

    // In-bin candidates strictly above threshold.
    float local = 0.0f;
    for (int i = tid; i < cnt; i += 1024) {
        float f = __uint_as_float(cand[i]);
        if (f > thresh) local += f;
    }
    #pragma unroll
    for (int o = 16; o; o >>= 1) local += __shfl_xor_sync(0xFFFFFFFFu, local, o);
    if (lane == 0) sredf[w] = local;
    __syncthreads();
    if (tid < 32) {
        float vv = sredf[tid];
        #pragma unroll
        for (int o = 16; o; o >>= 1) vv += __shfl_xor_sync(0xFFFFFFFFu, vv, o);
        if (tid == 0) {
            float neg = vv + s_above;
            float fnp = (float)s_np;
            float conf_total = s_possum / fnp + neg / (fnp * 3.0f);
            float loc_total  = s_locsum / (float)s_loccnt;
            g_batch[b] = conf_total + loc_total;
            __threadfence();
            int done = atomicAdd(&g_done, 1);
            s_islast = (done == BATCH - 1);
        }
    }
    __syncthreads();
    if (s_islast && tid < 32) {
        float t = g_batch[tid] + g_batch[tid + 32];
        #pragma unroll
        for (int o = 16; o; o >>= 1) t += __shfl_xor_sync(0xFFFFFFFFu, t, o);
        if (tid == 0) {
            out[0] = t * (1.0f / (float)BATCH);
            g_done = 0;                          // reset for next graph replay
        }
    }
}

// ---------------------------------------------------------------------------
extern "C" void kernel_launch(void* const* d_in, const int* in_sizes, int n_in,
                              void* d_out, int out_size) {
    const float* pred_conf = (const float*)d_in[0];
    const float* pred_loc  = (const float*)d_in[1];
    const float* gt_conf   = (const float*)d_in[2];
    const float* gt_loc    = (const float*)d_in[3];
    float* out = (float*)d_out;

    k_main<<<KM_CTAS, 256>>>(pred_conf, pred_loc, gt_conf, gt_loc);
    k_finish<<<BATCH, 1024>>>(out);
}